// round 8
// baseline (speedup 1.0000x reference)
#include <cuda_runtime.h>

#define BATCH   32
#define TSTEPS  1024
#define COLS    2048
#define SPLIT   4
#define THREADS 128            /* threads per CTA */
#define V       4              /* columns per thread (float4) */
#define WARPS   (THREADS / 32)
#define ROW4    (COLS / 4)     /* row stride in float4 = 512 */
#define DPF     16             /* x prefetch depth (time steps), power of 2 */

/* ---- helpers ---------------------------------------------------------- */

__device__ __forceinline__ unsigned smem_u32(const void* p) {
    unsigned a;
    asm("{ .reg .u64 t; cvta.to.shared.u64 t, %1; cvt.u32.u64 %0, t; }"
        : "=r"(a) : "l"(p));
    return a;
}
__device__ __forceinline__ unsigned long long lds_vol(unsigned addr) {
    unsigned long long v;
    asm volatile("ld.volatile.shared.b64 %0, [%1];" : "=l"(v) : "r"(addr));
    return v;
}
__device__ __forceinline__ void sts_vol(unsigned addr, unsigned long long v) {
    asm volatile("st.volatile.shared.b64 [%0], %1;" :: "r"(addr), "l"(v) : "memory");
}
/* Push {tag,value} into the same smem offset of cluster CTA `rank` (DSMEM). */
__device__ __forceinline__ void st_remote(unsigned local_addr, unsigned rank,
                                          unsigned long long v) {
    asm volatile(
        "{ .reg .b32 r;\n\t"
        "  mapa.shared::cluster.u32 r, %0, %1;\n\t"
        "  st.relaxed.cluster.shared::cluster.b64 [r], %2; }"
        :: "r"(local_addr), "r"(rank), "l"(v) : "memory");
}

__device__ __forceinline__ float smix(float a, float b) {
    float d = a - b;                      /* a - b           */
    float e = __expf(-d);                 /* MUFU.EX2 path   */
    float p = __fdividef(1.0f, 1.0f + e); /* MUFU.RCP path   */
    return fmaf(p, d, b);                 /* b + p*(a-b)     */
}

#define TAGV(f) ((1ull << 32) | (unsigned long long)__float_as_uint(f))

/* ---- kernel ------------------------------------------------------------ */

__global__ __launch_bounds__(THREADS, 1) __cluster_dims__(SPLIT, 1, 1)
void softscan_kernel(const float* __restrict__ x, float* __restrict__ out) {
    /* Mailboxes: one 8B tagged slot per time step -> no reuse, no sync needed. */
    __shared__ unsigned long long cluster_inbox[TSTEPS];          /* 8 KB  */
    __shared__ unsigned long long warp_seam[WARPS - 1][TSTEPS];   /* 24 KB */

    const int s    = blockIdx.x;          /* CTA rank within cluster/batch */
    const int b    = blockIdx.y;
    const int tid  = threadIdx.x;
    const int lane = tid & 31;
    const int warp = tid >> 5;
    const int col0 = (s * THREADS + tid) * V;

    /* zero mailboxes, then make them visible cluster-wide */
    for (int i = tid; i < TSTEPS; i += THREADS) cluster_inbox[i] = 0;
    #pragma unroll
    for (int w = 0; w < WARPS - 1; ++w)
        for (int i = tid; i < TSTEPS; i += THREADS) warp_seam[w][i] = 0;
    __syncthreads();
    asm volatile("barrier.cluster.arrive.aligned;" ::: "memory");
    asm volatile("barrier.cluster.wait.aligned;"   ::: "memory");

    const unsigned ci_addr   = smem_u32(cluster_inbox);
    const unsigned poll_addr = (warp > 0) ? smem_u32(&warp_seam[warp - 1][0]) : ci_addr;
    const unsigned seam_addr = (warp < WARPS - 1) ? smem_u32(&warp_seam[warp][0]) : 0;

    const bool producer = (tid == THREADS - 1) && (s != SPLIT - 1);
    const bool seamer   = (lane == 31) && (warp != WARPS - 1);
    const bool poller   = (lane == 0) && (warp > 0 || s > 0);
    const bool firstcol = (tid == 0) && (s == 0);

    const float4* xp = (const float4*)(x   + (size_t)b * TSTEPS * COLS + col0);
    float4*       op = (float4*)      (out + (size_t)b * TSTEPS * COLS + col0);

    /* ---- t = 0 ---- */
    float4 c = __ldcs(xp);
    __stcs(op, c);
    if (seamer)   sts_vol(seam_addr, TAGV(c.w));
    if (producer) st_remote(ci_addr, s + 1, TAGV(c.w));

    /* x prefetch ring: buf[k] holds row k+1 (so index == (t-1) & 15) */
    float4 buf[DPF];
    #pragma unroll
    for (int k = 0; k < DPF; ++k)
        buf[k] = __ldcs(xp + (size_t)(k + 1) * ROW4);

    /* ---- main loop: no __syncthreads; warps/CTAs self-skew via mailboxes ---- */
    for (int tb = 1; tb < TSTEPS; tb += DPF) {
        #pragma unroll
        for (int k = 0; k < DPF; ++k) {
            const int t = tb + k;            /* (t-1) & 15 == k by construction */
            if (t >= TSTEPS) break;

            float4 xv = buf[k];
            if (t + DPF < TSTEPS)
                buf[k] = __ldcs(xp + (size_t)(t + DPF) * ROW4);

            /* left neighbor's carry from step t-1 */
            float left = __shfl_up_sync(0xffffffffu, c.w, 1);
            if (poller) {
                unsigned long long v;
                unsigned a = poll_addr + 8u * (t - 1);
                do { v = lds_vol(a); } while (!(v >> 32));
                left = __uint_as_float((unsigned)v);
            }

            float4 nc;
            nc.x = firstcol ? (xv.x + c.x) : (xv.x + smix(c.x, left));
            nc.y = xv.y + smix(c.y, c.x);
            nc.z = xv.z + smix(c.z, c.y);
            nc.w = xv.w + smix(c.w, c.z);
            c = nc;

            __stcs(op + (size_t)t * ROW4, c);
            if (seamer)   sts_vol(seam_addr + 8u * t, TAGV(c.w));
            if (producer) st_remote(ci_addr + 8u * t, s + 1, TAGV(c.w));
        }
    }

    /* keep peer SMEM alive until all in-flight remote stores have landed */
    asm volatile("barrier.cluster.arrive.aligned;" ::: "memory");
    asm volatile("barrier.cluster.wait.aligned;"   ::: "memory");
}

/* ---- launch ------------------------------------------------------------ */

extern "C" void kernel_launch(void* const* d_in, const int* in_sizes, int n_in,
                              void* d_out, int out_size) {
    const float* x = (const float*)d_in[0];
    float* out = (float*)d_out;
    dim3 grid(SPLIT, BATCH);   /* 128 CTAs = 32 clusters of 4: single wave */
    softscan_kernel<<<grid, THREADS>>>(x, out);
}

// round 11
// speedup vs baseline: 1.5421x; 1.5421x over previous
#include <cuda_runtime.h>

#define BATCH   32
#define TSTEPS  1024
#define COLS    2048
#define SPLIT   4
#define THREADS 128            /* threads per CTA */
#define V       4              /* columns per thread (float4) */
#define WARPS   (THREADS / 32)
#define ROW4    (COLS / 4)     /* row stride in float4 = 512 */
#define DPF     8              /* x prefetch depth (time steps) */
#define CHUNK   8              /* relay chunk (steps per flush) */
#define NCH     (TSTEPS / CHUNK)

/* Relay storage: per (batch,block) lane, NCH chunks.
   Each chunk = 8 floats packed as 4 u64 + one u32 ready flag.  */
__device__ unsigned long long g_vals[BATCH * SPLIT * NCH * 4];
__device__ unsigned           g_flag[BATCH * SPLIT * NCH];

__device__ __forceinline__ void st_rlx64(unsigned long long* p, unsigned long long v) {
    asm volatile("st.relaxed.gpu.global.b64 [%0], %1;" :: "l"(p), "l"(v) : "memory");
}
__device__ __forceinline__ unsigned long long ld_rlx64(const unsigned long long* p) {
    unsigned long long v;
    asm volatile("ld.relaxed.gpu.global.b64 %0, [%1];" : "=l"(v) : "l"(p) : "memory");
    return v;
}
__device__ __forceinline__ void st_rel32(unsigned* p, unsigned v) {
    asm volatile("st.release.gpu.global.b32 [%0], %1;" :: "l"(p), "r"(v) : "memory");
}
__device__ __forceinline__ unsigned ld_acq32(const unsigned* p) {
    unsigned v;
    asm volatile("ld.acquire.gpu.global.b32 %0, [%1];" : "=r"(v) : "l"(p) : "memory");
    return v;
}

__device__ __forceinline__ float smix(float a, float b) {
    float d = a - b;
    float e = __expf(-d);                  /* MUFU.EX2 */
    float p = __fdividef(1.0f, 1.0f + e);  /* MUFU.RCP */
    return fmaf(p, d, b);
}

__device__ __forceinline__ unsigned long long pack2(float lo, float hi) {
    unsigned long long v;
    asm("mov.b64 %0, {%1, %2};" : "=l"(v) : "r"(__float_as_uint(lo)), "r"(__float_as_uint(hi)));
    return v;
}
__device__ __forceinline__ void unpack2(unsigned long long v, float* lo, float* hi) {
    unsigned a, b;
    asm("mov.b64 {%0, %1}, %2;" : "=r"(a), "=r"(b) : "l"(v));
    *lo = __uint_as_float(a); *hi = __uint_as_float(b);
}

__global__ __launch_bounds__(THREADS, 1)
void softscan_kernel(const float* __restrict__ x, float* __restrict__ out) {
    const int s    = blockIdx.x;          /* column-block within batch */
    const int b    = blockIdx.y;
    const int tid  = threadIdx.x;
    const int lane = tid & 31;
    const int warp = tid >> 5;
    const int col0 = (s * THREADS + tid) * V;

    __shared__ float sh[2][WARPS];        /* double-buffered warp seams */

    const float4* xp = (const float4*)(x   + (size_t)b * TSTEPS * COLS + col0);
    float4*       op = (float4*)      (out + (size_t)b * TSTEPS * COLS + col0);

    /* my outgoing relay lane / upstream incoming lane */
    const int my_lane_id = b * SPLIT + s;
    unsigned long long* my_vals = g_vals + (size_t)my_lane_id * NCH * 4;
    unsigned*           my_flag = g_flag + (size_t)my_lane_id * NCH;
    const unsigned long long* src_vals = g_vals + (size_t)(my_lane_id - 1) * NCH * 4;
    const unsigned*           src_flag = g_flag + (size_t)(my_lane_id - 1) * NCH;

    const bool producer = (tid == THREADS - 1) && (s != SPLIT - 1);
    const bool consumer = (tid == 0) && (s != 0);
    const bool firstcol = (tid == 0) && (s == 0);

    /* ---- t = 0 ---- */
    float4 c = __ldcs(xp);
    __stcs(op, c);
    if (lane == 31) sh[0][warp] = c.w;

    float pvals[CHUNK];                   /* producer's pending chunk */
    pvals[0] = c.w;

    float cvals[CHUNK];                   /* consumer's current chunk */
    float nvals[CHUNK];                   /* consumer's prefetched next chunk */
    bool  havenext = false;

    /* x prefetch ring: buf[k] holds row (t) with (t-1)&7 == k */
    float4 buf[DPF];
    #pragma unroll
    for (int k = 0; k < DPF; ++k)
        buf[k] = __ldcs(xp + (size_t)(k + 1) * ROW4);
    __syncthreads();

    for (int tb = 1; tb < TSTEPS; tb += CHUNK) {
        #pragma unroll
        for (int k = 0; k < CHUNK; ++k) {
            const int t = tb + k;         /* (t-1)&7 == k by construction */
            if (t >= TSTEPS) break;

            float4 xv = buf[k];
            if (t + DPF < TSTEPS)
                buf[k] = __ldcs(xp + (size_t)(t + DPF) * ROW4);

            /* left neighbor's carry from step t-1 */
            float left = __shfl_up_sync(0xffffffffu, c.w, 1);
            if (lane == 0) {
                if (warp > 0) {
                    left = sh[(t - 1) & 1][warp - 1];
                } else if (consumer) {
                    if (k == 0) {
                        /* need chunk (tb-1)/8 : use prefetched copy or fetch now */
                        if (havenext) {
                            #pragma unroll
                            for (int i = 0; i < CHUNK; ++i) cvals[i] = nvals[i];
                            havenext = false;
                        } else {
                            const int ci = (tb - 1) >> 3;
                            while (!ld_acq32(src_flag + ci)) { }
                            #pragma unroll
                            for (int i = 0; i < 4; ++i)
                                unpack2(ld_rlx64(src_vals + ci * 4 + i),
                                        &cvals[2 * i], &cvals[2 * i + 1]);
                        }
                    }
                    left = cvals[k];
                    if (k == 4) {
                        /* opportunistic prefetch of the next chunk */
                        const int ci = ((tb - 1) >> 3) + 1;
                        if (ci < NCH && ld_acq32(src_flag + ci)) {
                            #pragma unroll
                            for (int i = 0; i < 4; ++i)
                                unpack2(ld_rlx64(src_vals + ci * 4 + i),
                                        &nvals[2 * i], &nvals[2 * i + 1]);
                            havenext = true;
                        }
                    }
                }
            }

            /* all 4 mixes read OLD carries -> parallel inside the step */
            float4 nc;
            nc.x = firstcol ? (xv.x + c.x) : (xv.x + smix(c.x, left));
            nc.y = xv.y + smix(c.y, c.x);
            nc.z = xv.z + smix(c.z, c.y);
            nc.w = xv.w + smix(c.w, c.z);
            c = nc;

            __stcs(op + (size_t)t * ROW4, c);
            if (lane == 31) sh[t & 1][warp] = c.w;

            if (producer) {
                pvals[(k + 1) & 7] = c.w;         /* slot (t & 7) */
                if (((k + 1) & 7) == 7) {         /* t&7 == 7: flush chunk t>>3 */
                    const int ci = t >> 3;
                    st_rlx64(my_vals + ci * 4 + 0, pack2(pvals[0], pvals[1]));
                    st_rlx64(my_vals + ci * 4 + 1, pack2(pvals[2], pvals[3]));
                    st_rlx64(my_vals + ci * 4 + 2, pack2(pvals[4], pvals[5]));
                    st_rlx64(my_vals + ci * 4 + 3, pack2(pvals[6], pvals[7]));
                    st_rel32(my_flag + ci, 1u);
                }
            }
            __syncthreads();
        }
    }
}

extern "C" void kernel_launch(void* const* d_in, const int* in_sizes, int n_in,
                              void* d_out, int out_size) {
    const float* x = (const float*)d_in[0];
    float* out = (float*)d_out;

    /* Reset relay flags every launch (captured memset node -> replay-safe). */
    void* flag_ptr = nullptr;
    cudaGetSymbolAddress(&flag_ptr, g_flag);
    cudaMemsetAsync(flag_ptr, 0, sizeof(unsigned) * BATCH * SPLIT * NCH, 0);

    dim3 grid(SPLIT, BATCH);   /* 128 blocks <= 148 SMs: single wave, deadlock-free */
    softscan_kernel<<<grid, THREADS>>>(x, out);
}